// round 2
// baseline (speedup 1.0000x reference)
#include <cuda_runtime.h>
#include <cstdint>

#define BATCH 128
#define T1    196
#define T2    392      // 2*T
#define ENC   1024
#define DEC   512
#define VV    98       // visible tokens
#define MM    294      // masked tokens

// scratch: visible token ids per (b, v)
__device__ int g_vis[BATCH * VV];
__device__ int g_is64;

// ---------------------------------------------------------------------------
// K0: detect masked_ids dtype (int32 vs int64). For int64, ids < 392 => every
// high 32-bit word is 0. For int32, odd-index words are random ids (nonzero
// with overwhelming probability). Scan first 1000 int32 words (4000B, safe
// under either layout since min buffer = 37632*4 B).
// ---------------------------------------------------------------------------
__global__ void detect_dtype_kernel(const int* __restrict__ mids_w) {
    __shared__ int any;
    if (threadIdx.x == 0) any = 0;
    __syncthreads();
    int acc = 0;
    for (int i = 1 + 2 * threadIdx.x; i < 1000; i += 2 * blockDim.x)
        acc |= mids_w[i];
    if (acc) atomicOr(&any, 1);
    __syncthreads();
    if (threadIdx.x == 0) g_is64 = (any == 0) ? 1 : 0;
}

// ---------------------------------------------------------------------------
// K1: per-batch visibility map. flag[t]=1 unless masked; block scan gives the
// rank of each visible t; g_vis[b*VV + rank] = t (ascending, matching argsort).
// ---------------------------------------------------------------------------
__global__ void build_map_kernel(const void* __restrict__ masked_ids) {
    __shared__ int flag[T2];
    __shared__ int s[512];
    const int b = blockIdx.x;
    const int tid = threadIdx.x;

    if (tid < T2) flag[tid] = 1;
    __syncthreads();

    const int is64 = g_is64;
    for (int i = tid; i < MM; i += 512) {
        int id;
        if (is64) id = (int)((const long long*)masked_ids)[(size_t)b * MM + i];
        else      id = ((const int*)masked_ids)[(size_t)b * MM + i];
        flag[id] = 0;
    }
    __syncthreads();

    const int f = (tid < T2) ? flag[tid] : 0;
    s[tid] = f;
    __syncthreads();
    // Hillis-Steele inclusive scan over 512
    #pragma unroll
    for (int off = 1; off < 512; off <<= 1) {
        int v = (tid >= off) ? s[tid - off] : 0;
        __syncthreads();
        s[tid] += v;
        __syncthreads();
    }
    if (f) g_vis[b * VV + (s[tid] - f)] = tid;
}

// ---------------------------------------------------------------------------
// K2: fill entire output with mask_token + pos_embed + view_embed.
// Value depends only on (t, d): compute once, broadcast-store to all 128 b.
// ---------------------------------------------------------------------------
__global__ void fill_kernel(const float* __restrict__ mask_token,
                            const float* __restrict__ pos_embed,
                            const float* __restrict__ view_embed,
                            float4* __restrict__ out) {
    const int D4 = DEC / 4;  // 128
    int idx = blockIdx.x * blockDim.x + threadIdx.x;  // t*D4 + d4
    if (idx >= T2 * D4) return;
    const int t  = idx / D4;
    const int d4 = idx - t * D4;

    const float4* mt4  = (const float4*)mask_token;
    const float4* pos4 = (const float4*)pos_embed;
    const float4* ve4  = (const float4*)view_embed;

    float4 m = mt4[d4];
    float4 p = pos4[idx];
    float4 v = ve4[(t >= T1 ? D4 : 0) + d4];
    float4 val = make_float4(m.x + p.x + v.x, m.y + p.y + v.y,
                             m.z + p.z + v.z, m.w + p.w + v.w);
    const size_t bstride = (size_t)T2 * D4;
    #pragma unroll 4
    for (int b = 0; b < BATCH; ++b)
        out[(size_t)b * bstride + idx] = val;
}

// ---------------------------------------------------------------------------
// K3: SGEMM (M=12544, N=512, K=1024) with fused scatter epilogue.
// A = x (row-major, K contiguous), B = W (row-major DECxENC, K contiguous) =>
// C[m][n] = dot(x[m,:], W[n,:]).  BM=BN=128, BK=8, 256 thr, 8x8 micro-tile.
// Epilogue: m -> (b, v); t = g_vis[b][v]; out[b][t][n] = acc + bias + pos + ve.
// ---------------------------------------------------------------------------
__global__ __launch_bounds__(256, 2)
void gemm_scatter_kernel(const float* __restrict__ x,
                         const float* __restrict__ W,
                         const float* __restrict__ bias,
                         const float* __restrict__ pos_embed,
                         const float* __restrict__ view_embed,
                         float* __restrict__ out) {
    constexpr int BM = 128, BN = 128, BK = 8;
    __shared__ float As[BK][BM + 4];
    __shared__ float Bs[BK][BN + 4];

    const int tid = threadIdx.x;
    const int m0 = blockIdx.y * BM;
    const int n0 = blockIdx.x * BN;

    const int ldRow = tid >> 1;          // 0..127
    const int ldK   = (tid & 1) * 4;     // 0 or 4
    const int tx = tid & 15, ty = tid >> 4;
    const int tm = ty * 8, tn = tx * 8;

    float acc[8][8] = {};

    const float* Aptr = x + (size_t)(m0 + ldRow) * ENC + ldK;
    const float* Bptr = W + (size_t)(n0 + ldRow) * ENC + ldK;

    float4 a4 = *(const float4*)(Aptr);
    float4 b4 = *(const float4*)(Bptr);

    for (int k0 = 0; k0 < ENC; k0 += BK) {
        As[ldK + 0][ldRow] = a4.x; As[ldK + 1][ldRow] = a4.y;
        As[ldK + 2][ldRow] = a4.z; As[ldK + 3][ldRow] = a4.w;
        Bs[ldK + 0][ldRow] = b4.x; Bs[ldK + 1][ldRow] = b4.y;
        Bs[ldK + 2][ldRow] = b4.z; Bs[ldK + 3][ldRow] = b4.w;
        __syncthreads();

        if (k0 + BK < ENC) {   // prefetch next tile into registers
            a4 = *(const float4*)(Aptr + k0 + BK);
            b4 = *(const float4*)(Bptr + k0 + BK);
        }

        #pragma unroll
        for (int k = 0; k < BK; ++k) {
            float4 a0 = *(const float4*)&As[k][tm];
            float4 a1 = *(const float4*)&As[k][tm + 4];
            float4 c0 = *(const float4*)&Bs[k][tn];
            float4 c1 = *(const float4*)&Bs[k][tn + 4];
            float ar[8] = {a0.x, a0.y, a0.z, a0.w, a1.x, a1.y, a1.z, a1.w};
            float br[8] = {c0.x, c0.y, c0.z, c0.w, c1.x, c1.y, c1.z, c1.w};
            #pragma unroll
            for (int i = 0; i < 8; ++i)
                #pragma unroll
                for (int j = 0; j < 8; ++j)
                    acc[i][j] = fmaf(ar[i], br[j], acc[i][j]);
        }
        __syncthreads();
    }

    // fused scatter epilogue
    #pragma unroll
    for (int i = 0; i < 8; ++i) {
        const int m = m0 + tm + i;
        const int bIdx = m / VV;
        const int v = m - bIdx * VV;
        const int t = g_vis[bIdx * VV + v];
        const float* vePtr = view_embed + (t >= T1 ? DEC : 0);
        const size_t ob = ((size_t)bIdx * T2 + t) * DEC + n0 + tn;
        const size_t pb = (size_t)t * DEC + n0 + tn;
        #pragma unroll
        for (int j4 = 0; j4 < 2; ++j4) {
            const int n = n0 + tn + j4 * 4;
            float4 bi = *(const float4*)(bias + n);
            float4 po = *(const float4*)(pos_embed + pb + j4 * 4);
            float4 ve = *(const float4*)(vePtr + n);
            float4 r;
            r.x = acc[i][j4 * 4 + 0] + bi.x + po.x + ve.x;
            r.y = acc[i][j4 * 4 + 1] + bi.y + po.y + ve.y;
            r.z = acc[i][j4 * 4 + 2] + bi.z + po.z + ve.z;
            r.w = acc[i][j4 * 4 + 3] + bi.w + po.w + ve.w;
            *(float4*)(out + ob + j4 * 4) = r;
        }
    }
}

// ---------------------------------------------------------------------------
extern "C" void kernel_launch(void* const* d_in, const int* in_sizes, int n_in,
                              void* d_out, int out_size) {
    const float* x          = (const float*)d_in[0];
    const void*  masked_ids = d_in[1];
    const float* W          = (const float*)d_in[2];
    const float* bias       = (const float*)d_in[3];
    const float* mask_token = (const float*)d_in[4];
    const float* pos_embed  = (const float*)d_in[5];
    const float* view_embed = (const float*)d_in[6];
    float* out = (float*)d_out;

    detect_dtype_kernel<<<1, 256>>>((const int*)masked_ids);
    build_map_kernel<<<BATCH, 512>>>(masked_ids);

    const int fill_items = T2 * (DEC / 4);
    fill_kernel<<<(fill_items + 255) / 256, 256>>>(mask_token, pos_embed,
                                                   view_embed, (float4*)out);

    dim3 grid(DEC / 128, (BATCH * VV) / 128);  // (4, 98)
    gemm_scatter_kernel<<<grid, 256>>>(x, W, bias, pos_embed, view_embed, out);
}

// round 4
// speedup vs baseline: 2.9090x; 2.9090x over previous
#include <cuda_runtime.h>
#include <cstdint>

#define BATCH 128
#define T1    196
#define T2    392
#define ENC   1024
#define DEC   512
#define VV    98
#define MM    294

// GEMM tiles
#define BM 128
#define BN 128
#define BK 32                 // K floats per stage (128 B rows)
#define NSLAB (ENC / BK)      // 32
#define A_STAGE (BM * 128)    // 16 KB
#define B_STAGE (BN * 128)    // 16 KB
#define SMEM_DYN (2 * (A_STAGE + B_STAGE))  // 64 KB

__device__ int g_vis[BATCH * VV];
__device__ int g_is64;

// ---------------------------------------------------------------------------
__device__ __forceinline__ uint32_t smem_u32(const void* p) {
    uint32_t a;
    asm("{ .reg .u64 t; cvta.to.shared.u64 t, %1; cvt.u32.u64 %0, t; }"
        : "=r"(a) : "l"(p));
    return a;
}
__device__ __forceinline__ void cp16(uint32_t dst, const void* src) {
    asm volatile("cp.async.cg.shared.global [%0], [%1], 16;"
                 :: "r"(dst), "l"(src));
}
#define CP_COMMIT() asm volatile("cp.async.commit_group;" ::: "memory")
#define CP_WAIT(n)  asm volatile("cp.async.wait_group %0;" :: "n"(n) : "memory")

__device__ __forceinline__ void ldsm4(uint32_t* r, uint32_t addr) {
    asm volatile("ldmatrix.sync.aligned.m8n8.x4.shared.b16 {%0,%1,%2,%3}, [%4];"
                 : "=r"(r[0]), "=r"(r[1]), "=r"(r[2]), "=r"(r[3]) : "r"(addr));
}
__device__ __forceinline__ void mma_tf32(float* c, const uint32_t* a,
                                         uint32_t b0, uint32_t b1) {
    asm volatile(
        "mma.sync.aligned.m16n8k8.row.col.f32.tf32.tf32.f32 "
        "{%0,%1,%2,%3}, {%4,%5,%6,%7}, {%8,%9}, {%0,%1,%2,%3};"
        : "+f"(c[0]), "+f"(c[1]), "+f"(c[2]), "+f"(c[3])
        : "r"(a[0]), "r"(a[1]), "r"(a[2]), "r"(a[3]), "r"(b0), "r"(b1));
}

// ---------------------------------------------------------------------------
// K0: detect masked_ids dtype (int32 vs int64)
// ---------------------------------------------------------------------------
__global__ void detect_dtype_kernel(const int* __restrict__ mids_w) {
    __shared__ int any;
    if (threadIdx.x == 0) any = 0;
    __syncthreads();
    int acc = 0;
    for (int i = 1 + 2 * threadIdx.x; i < 1000; i += 2 * blockDim.x)
        acc |= mids_w[i];
    if (acc) atomicOr(&any, 1);
    __syncthreads();
    if (threadIdx.x == 0) g_is64 = (any == 0) ? 1 : 0;
}

// ---------------------------------------------------------------------------
// K1: per-batch visibility map (sorted complement of masked ids)
// ---------------------------------------------------------------------------
__global__ void build_map_kernel(const void* __restrict__ masked_ids) {
    __shared__ int flag[T2];
    __shared__ int s[512];
    const int b = blockIdx.x;
    const int tid = threadIdx.x;

    if (tid < T2) flag[tid] = 1;
    __syncthreads();

    const int is64 = g_is64;
    for (int i = tid; i < MM; i += 512) {
        int id;
        if (is64) id = (int)((const long long*)masked_ids)[(size_t)b * MM + i];
        else      id = ((const int*)masked_ids)[(size_t)b * MM + i];
        flag[id] = 0;
    }
    __syncthreads();

    const int f = (tid < T2) ? flag[tid] : 0;
    s[tid] = f;
    __syncthreads();
    #pragma unroll
    for (int off = 1; off < 512; off <<= 1) {
        int v = (tid >= off) ? s[tid - off] : 0;
        __syncthreads();
        s[tid] += v;
        __syncthreads();
    }
    if (f) g_vis[b * VV + (s[tid] - f)] = tid;
}

// ---------------------------------------------------------------------------
// K2: fill whole output with mask_token + pos_embed + view_embed
// ---------------------------------------------------------------------------
__global__ void fill_kernel(const float* __restrict__ mask_token,
                            const float* __restrict__ pos_embed,
                            const float* __restrict__ view_embed,
                            float4* __restrict__ out) {
    const int D4 = DEC / 4;
    int idx = blockIdx.x * blockDim.x + threadIdx.x;
    if (idx >= T2 * D4) return;
    const int t  = idx / D4;
    const int d4 = idx - t * D4;

    const float4* mt4  = (const float4*)mask_token;
    const float4* pos4 = (const float4*)pos_embed;
    const float4* ve4  = (const float4*)view_embed;

    float4 m = mt4[d4];
    float4 p = pos4[idx];
    float4 v = ve4[(t >= T1 ? D4 : 0) + d4];
    float4 val = make_float4(m.x + p.x + v.x, m.y + p.y + v.y,
                             m.z + p.z + v.z, m.w + p.w + v.w);
    const size_t bstride = (size_t)T2 * D4;
    #pragma unroll 4
    for (int b = 0; b < BATCH; ++b)
        out[(size_t)b * bstride + idx] = val;
}

// ---------------------------------------------------------------------------
// K3: tf32 mma.sync GEMM (M=12544, N=512, K=1024) + fused scatter epilogue.
// A/B K-major in smem (128B rows, SW128). ldmatrix.x4 feeds both operands.
// 8 warps: 4m x 2n, warp tile 32x64. 2-stage cp.async pipeline.
// ---------------------------------------------------------------------------
__global__ __launch_bounds__(256, 2)
void gemm_tc_kernel(const float* __restrict__ x,
                    const float* __restrict__ W,
                    const float* __restrict__ bias,
                    const float* __restrict__ pos_embed,
                    const float* __restrict__ view_embed,
                    float* __restrict__ out) {
    extern __shared__ char smem_raw[];
    const uint32_t A0 = smem_u32(smem_raw);
    const uint32_t B0 = A0 + 2 * A_STAGE;

    const int tid = threadIdx.x;
    const int wid = tid >> 5, lid = tid & 31;
    const int wm = wid >> 1, wn = wid & 1;
    const int m0 = blockIdx.y * BM;
    const int n0 = blockIdx.x * BN;

    // ---- loader mapping: thread -> row, 4 chunks of 16B
    const int rA = tid >> 1;
    const int q0 = (tid & 1) * 4;
    const uint32_t rsw = (rA & 7) << 4;
    const float* xsrc = x + (size_t)(m0 + rA) * ENC + q0 * 4;
    const float* wsrc = W + (size_t)(n0 + rA) * ENC + q0 * 4;
    const uint32_t adst = rA * 128 + ((q0 * 16) ^ rsw);  // +16B chunks stay in-row
    // note: chunks q0..q0+3 -> offsets (q*16)^rsw; q*16 spans bits 4..6 only

    // ---- fragment addresses (per thread)
    // A: tile = lid>>3; row = wm*32 + f*16 + ((tile&1)<<3) + (lid&7); kb16 = (tile>>1)*16
    const int a_row0 = wm * 32 + ((lid >> 3 & 1) << 3) + (lid & 7);
    const uint32_t a_kb = ((lid >> 4) & 1) * 16;
    const uint32_t a_swz0 = (a_row0 & 7) << 4;
    const uint32_t a_base0 = a_row0 * 128;           // f adds 16*128
    // B: tile = lid>>3; row = wn*64 + p*16 + ((tile>>1)<<3) + (lid&7); kb16 = (tile&1)*16
    const int b_row0 = wn * 64 + (((lid >> 4) & 1) << 3) + (lid & 7);
    const uint32_t b_kb = ((lid >> 3) & 1) * 16;
    const uint32_t b_swz0 = (b_row0 & 7) << 4;
    const uint32_t b_base0 = b_row0 * 128;           // p adds 16*128

    float acc[2][8][4];
    #pragma unroll
    for (int f = 0; f < 2; f++)
        #pragma unroll
        for (int nf = 0; nf < 8; nf++)
            #pragma unroll
            for (int i = 0; i < 4; i++) acc[f][nf][i] = 0.f;

    // ---- prologue: stages 0,1
    #pragma unroll
    for (int st = 0; st < 2; st++) {
        #pragma unroll
        for (int i = 0; i < 4; i++) {
            cp16(A0 + st * A_STAGE + (adst ^ (i * 16)), xsrc + st * BK + i * 4);
            cp16(B0 + st * B_STAGE + (adst ^ (i * 16)), wsrc + st * BK + i * 4);
        }
        CP_COMMIT();
    }

    for (int k = 0; k < NSLAB; k++) {
        const int s = k & 1;
        CP_WAIT(1);
        __syncthreads();

        const uint32_t As = A0 + s * A_STAGE;
        const uint32_t Bs = B0 + s * B_STAGE;
        #pragma unroll
        for (int ks = 0; ks < 4; ks++) {
            const uint32_t k0b = ks * 32;
            uint32_t a[2][4], b[4][4];
            #pragma unroll
            for (int f = 0; f < 2; f++)
                ldsm4(a[f], As + a_base0 + f * (16 * 128) +
                             ((a_kb + k0b) ^ a_swz0));
            #pragma unroll
            for (int p = 0; p < 4; p++)
                ldsm4(b[p], Bs + b_base0 + p * (16 * 128) +
                             ((b_kb + k0b) ^ b_swz0));
            #pragma unroll
            for (int f = 0; f < 2; f++)
                #pragma unroll
                for (int p = 0; p < 4; p++) {
                    mma_tf32(acc[f][2 * p],     a[f], b[p][0], b[p][1]);
                    mma_tf32(acc[f][2 * p + 1], a[f], b[p][2], b[p][3]);
                }
        }
        __syncthreads();

        if (k + 2 < NSLAB) {
            #pragma unroll
            for (int i = 0; i < 4; i++) {
                cp16(A0 + s * A_STAGE + (adst ^ (i * 16)),
                     xsrc + (k + 2) * BK + i * 4);
                cp16(B0 + s * B_STAGE + (adst ^ (i * 16)),
                     wsrc + (k + 2) * BK + i * 4);
            }
        }
        CP_COMMIT();
    }

    // ---- fused scatter epilogue
    const int g  = lid >> 2;
    const int nc = 2 * (lid & 3);
    const int nbase = n0 + wn * 64;
    #pragma unroll
    for (int f = 0; f < 2; f++) {
        #pragma unroll
        for (int h = 0; h < 2; h++) {
            const int m = m0 + wm * 32 + f * 16 + h * 8 + g;
            const int b = m / VV;
            const int t = g_vis[m];
            const float* ve   = view_embed + (t >= T1 ? DEC : 0) + nbase;
            const float* bi   = bias + nbase;
            const float* prow = pos_embed + (size_t)t * DEC + nbase;
            float* orow = out + ((size_t)b * T2 + t) * DEC + nbase;
            #pragma unroll
            for (int nf = 0; nf < 8; nf++) {
                const int n = nf * 8 + nc;
                float2 biv = *(const float2*)(bi + n);
                float2 pov = *(const float2*)(prow + n);
                float2 vev = *(const float2*)(ve + n);
                float2 r;
                r.x = acc[f][nf][2 * h + 0] + biv.x + pov.x + vev.x;
                r.y = acc[f][nf][2 * h + 1] + biv.y + pov.y + vev.y;
                *(float2*)(orow + n) = r;
            }
        }
    }
}

// ---------------------------------------------------------------------------
extern "C" void kernel_launch(void* const* d_in, const int* in_sizes, int n_in,
                              void* d_out, int out_size) {
    const float* x          = (const float*)d_in[0];
    const void*  masked_ids = d_in[1];
    const float* W          = (const float*)d_in[2];
    const float* bias       = (const float*)d_in[3];
    const float* mask_token = (const float*)d_in[4];
    const float* pos_embed  = (const float*)d_in[5];
    const float* view_embed = (const float*)d_in[6];
    float* out = (float*)d_out;

    detect_dtype_kernel<<<1, 256>>>((const int*)masked_ids);
    build_map_kernel<<<BATCH, 512>>>(masked_ids);

    const int fill_items = T2 * (DEC / 4);
    fill_kernel<<<(fill_items + 255) / 256, 256>>>(mask_token, pos_embed,
                                                   view_embed, (float4*)out);

    static int smem_set = 0;
    if (!smem_set) {
        cudaFuncSetAttribute(gemm_tc_kernel,
                             cudaFuncAttributeMaxDynamicSharedMemorySize, SMEM_DYN);
        smem_set = 1;
    }
    dim3 grid(DEC / BN, (BATCH * VV) / BM);  // (4, 98)
    gemm_tc_kernel<<<grid, 256, SMEM_DYN>>>(x, W, bias, pos_embed, view_embed, out);
}